// round 6
// baseline (speedup 1.0000x reference)
#include <cuda_runtime.h>
#include <cuda_bf16.h>
#include <math.h>
#include <cstdint>

#define Bb 16
#define Tt 256
#define Ee 512
#define Hh 1024
#define Vv 32000
#define G3 3072
#define Mm (Bb*Tt)   // 4096

#define GRU_BLOCKS 128

// ---- scratch ----
__device__ float g_gi[(size_t)Mm*G3];
__device__ float g_hs[(size_t)Mm*Hh];
__device__ __nv_bfloat16 g_W1b[(size_t)Hh*Hh];
__device__ __nv_bfloat16 g_W2b[(size_t)Vv*Hh];
__device__ __nv_bfloat16 g_hsb[(size_t)Mm*Hh];
__device__ __nv_bfloat16 g_yb [(size_t)Mm*Hh];
__device__ unsigned g_cntA = 0, g_genA = 0;
__device__ unsigned g_cntB = 0, g_genB = 0;

__device__ __forceinline__ uint32_t smem_u32(const void* p) {
    uint32_t a;
    asm("{ .reg .u64 t; cvta.to.shared.u64 t, %1; cvt.u32.u64 %0, t; }" : "=r"(a) : "l"(p));
    return a;
}
__device__ __forceinline__ void fma2(unsigned long long& d, unsigned long long a, unsigned long long b) {
    asm("fma.rn.f32x2 %0, %1, %2, %0;" : "+l"(d) : "l"(a), "l"(b));
}
__device__ __forceinline__ float sum2(unsigned long long v) {
    float lo, hi;
    asm("mov.b64 {%0, %1}, %2;" : "=f"(lo), "=f"(hi) : "l"(v));
    return lo + hi;
}

// ================= fp32 -> bf16 (weights only) =================
__global__ void f2bf_kernel(const float* __restrict__ x, __nv_bfloat16* __restrict__ o, int n4)
{
    int i = blockIdx.x * blockDim.x + threadIdx.x;
    if (i >= n4) return;
    float4 v = ((const float4*)x)[i];
    __nv_bfloat162* p = (__nv_bfloat162*)o + i * 2;
    p[0] = __floats2bfloat162_rn(v.x, v.y);
    p[1] = __floats2bfloat162_rn(v.z, v.w);
}

// ================= HMMA bf16 GEMM =================
#define HG_STRIDE  40
#define HG_ATILE   (128 * HG_STRIDE * 2)
#define HG_STAGE   (2 * HG_ATILE)
#define HG_SMEM    (2 * HG_STAGE)

__device__ __forceinline__ void ldsm_x4(uint32_t* r, uint32_t addr) {
    asm volatile("ldmatrix.sync.aligned.m8n8.x4.shared.b16 {%0,%1,%2,%3}, [%4];"
                 : "=r"(r[0]), "=r"(r[1]), "=r"(r[2]), "=r"(r[3]) : "r"(addr));
}
__device__ __forceinline__ void mma16816(float* d, const uint32_t* a, uint32_t b0, uint32_t b1) {
    asm volatile("mma.sync.aligned.m16n8k16.row.col.f32.bf16.bf16.f32 "
                 "{%0,%1,%2,%3}, {%4,%5,%6,%7}, {%8,%9}, {%0,%1,%2,%3};"
                 : "+f"(d[0]), "+f"(d[1]), "+f"(d[2]), "+f"(d[3])
                 : "r"(a[0]), "r"(a[1]), "r"(a[2]), "r"(a[3]), "r"(b0), "r"(b1));
}
__device__ __forceinline__ void cp_async16(uint32_t saddr, const void* gaddr) {
    asm volatile("cp.async.cg.shared.global [%0], [%1], 16;" :: "r"(saddr), "l"(gaddr));
}

__global__ void __launch_bounds__(256) hmma_gemm_kernel(
    const __nv_bfloat16* __restrict__ A,
    const __nv_bfloat16* __restrict__ Bm,
    const float* __restrict__ bias,
    void* __restrict__ Cv,
    int M, int N, int K, int do_relu, int out_bf16)
{
    extern __shared__ char smem[];
    const uint32_t sb = smem_u32(smem);
    const int tid  = threadIdx.x;
    const int wid  = tid >> 5;
    const int lane = tid & 31;
    const int bn = blockIdx.x, bm = blockIdx.y;

    const int warp_m = wid & 3;
    const int warp_n = wid >> 2;

    float d[2][8][4];
#pragma unroll
    for (int i = 0; i < 2; i++)
#pragma unroll
        for (int j = 0; j < 8; j++)
#pragma unroll
            for (int q = 0; q < 4; q++) d[i][j][q] = 0.f;

    const int NK = K >> 5;
    const int lmat = lane >> 3;
    const int lrow = lane & 7;

    auto load_stage = [&](int it, int buf) {
        const int kt = it << 5;
        const uint32_t sa = sb + buf * HG_STAGE;
        const uint32_t sbB = sa + HG_ATILE;
#pragma unroll
        for (int s = 0; s < 2; s++) {
            const int idx = tid + s * 256;
            const int row = idx >> 2, c = idx & 3;
            cp_async16(sa + row * (HG_STRIDE*2) + c * 16,
                       A + (size_t)(bm * 128 + row) * K + kt + c * 8);
            cp_async16(sbB + row * (HG_STRIDE*2) + c * 16,
                       Bm + (size_t)(bn * 128 + row) * K + kt + c * 8);
        }
        asm volatile("cp.async.commit_group;");
    };

    load_stage(0, 0);

    for (int it = 0; it < NK; it++) {
        if (it + 1 < NK) {
            load_stage(it + 1, (it + 1) & 1);
            asm volatile("cp.async.wait_group 1;");
        } else {
            asm volatile("cp.async.wait_group 0;");
        }
        __syncthreads();

        const uint32_t sa  = sb + (it & 1) * HG_STAGE;
        const uint32_t sbB = sa + HG_ATILE;

#pragma unroll
        for (int ks = 0; ks < 2; ks++) {
            uint32_t a[2][4];
#pragma unroll
            for (int mt = 0; mt < 2; mt++) {
                const int row = warp_m * 32 + mt * 16 + (lmat & 1) * 8 + lrow;
                const int c   = ks * 2 + (lmat >> 1);
                ldsm_x4(a[mt], sa + row * (HG_STRIDE*2) + c * 16);
            }
            uint32_t b[4][4];
#pragma unroll
            for (int nt = 0; nt < 4; nt++) {
                const int n = warp_n * 64 + nt * 16 + (lmat >> 1) * 8 + lrow;
                const int c = ks * 2 + (lmat & 1);
                ldsm_x4(b[nt], sbB + n * (HG_STRIDE*2) + c * 16);
            }
#pragma unroll
            for (int mt = 0; mt < 2; mt++)
#pragma unroll
                for (int nt = 0; nt < 4; nt++) {
                    mma16816(d[mt][nt*2+0], a[mt], b[nt][0], b[nt][1]);
                    mma16816(d[mt][nt*2+1], a[mt], b[nt][2], b[nt][3]);
                }
        }
        __syncthreads();
    }

#pragma unroll
    for (int mt = 0; mt < 2; mt++) {
        const int row0 = bm * 128 + warp_m * 32 + mt * 16 + (lane >> 2);
#pragma unroll
        for (int nt8 = 0; nt8 < 8; nt8++) {
            const int col = bn * 128 + warp_n * 64 + nt8 * 8 + (lane & 3) * 2;
            const float b0 = bias[col], b1 = bias[col + 1];
            float2 v0, v1;
            v0.x = d[mt][nt8][0] + b0; v0.y = d[mt][nt8][1] + b1;
            v1.x = d[mt][nt8][2] + b0; v1.y = d[mt][nt8][3] + b1;
            if (do_relu) {
                v0.x = fmaxf(v0.x, 0.f); v0.y = fmaxf(v0.y, 0.f);
                v1.x = fmaxf(v1.x, 0.f); v1.y = fmaxf(v1.y, 0.f);
            }
            if (out_bf16) {
                __nv_bfloat162* C = (__nv_bfloat162*)Cv;
                C[((size_t)row0 * N + col) >> 1]       = __floats2bfloat162_rn(v0.x, v0.y);
                C[((size_t)(row0 + 8) * N + col) >> 1] = __floats2bfloat162_rn(v1.x, v1.y);
            } else {
                float* C = (float*)Cv;
                *(float2*)(C + (size_t)row0 * N + col)       = v0;
                *(float2*)(C + (size_t)(row0 + 8) * N + col) = v1;
            }
        }
    }
}

// ================= fp32 SIMT SGEMM (gi, gathered A) =================
__global__ void sgemm_kernel(const float* __restrict__ A,
                             const float* __restrict__ Bm,
                             const float* __restrict__ bias,
                             float* __restrict__ C,
                             int M, int N, int K,
                             const int* __restrict__ gidx,
                             int do_relu)
{
    __shared__ float As[8][128];
    __shared__ float Bs[8][128];

    const int tid = threadIdx.x;
    const int bn  = blockIdx.x;
    const int bm  = blockIdx.y;

    const int lrow = tid >> 1;
    const int kq   = (tid & 1) * 4;

    const int arow_g = bm * 128 + lrow;
    const float* Ap = gidx ? (A + (size_t)gidx[arow_g] * K)
                           : (A + (size_t)arow_g * K);
    const float* Bp = Bm + (size_t)(bn * 128 + lrow) * K;

    const int tx = tid & 15;
    const int ty = tid >> 4;
    const int m0 = ty * 8;
    const int n0 = tx * 8;

    float acc[8][8];
#pragma unroll
    for (int i = 0; i < 8; i++)
#pragma unroll
        for (int j = 0; j < 8; j++) acc[i][j] = 0.f;

    for (int kt = 0; kt < K; kt += 8) {
        float4 av = *(const float4*)(Ap + kt + kq);
        float4 bv = *(const float4*)(Bp + kt + kq);
        As[kq+0][lrow] = av.x; As[kq+1][lrow] = av.y;
        As[kq+2][lrow] = av.z; As[kq+3][lrow] = av.w;
        Bs[kq+0][lrow] = bv.x; Bs[kq+1][lrow] = bv.y;
        Bs[kq+2][lrow] = bv.z; Bs[kq+3][lrow] = bv.w;
        __syncthreads();

#pragma unroll
        for (int kk = 0; kk < 8; kk++) {
            float4 a0 = *(const float4*)&As[kk][m0];
            float4 a1 = *(const float4*)&As[kk][m0 + 4];
            float4 b0 = *(const float4*)&Bs[kk][n0];
            float4 b1 = *(const float4*)&Bs[kk][n0 + 4];
            float am[8] = {a0.x,a0.y,a0.z,a0.w,a1.x,a1.y,a1.z,a1.w};
            float bb[8] = {b0.x,b0.y,b0.z,b0.w,b1.x,b1.y,b1.z,b1.w};
#pragma unroll
            for (int i = 0; i < 8; i++)
#pragma unroll
                for (int j = 0; j < 8; j++)
                    acc[i][j] = fmaf(am[i], bb[j], acc[i][j]);
        }
        __syncthreads();
    }

    const int ncol0 = bn * 128 + n0;
    float bsv[8];
#pragma unroll
    for (int j = 0; j < 8; j++) bsv[j] = bias[ncol0 + j];

#pragma unroll
    for (int i = 0; i < 8; i++) {
        const int m = bm * 128 + m0 + i;
        float* crow = C + (size_t)m * N + ncol0;
#pragma unroll
        for (int jq = 0; jq < 2; jq++) {
            float4 v;
            v.x = acc[i][jq*4+0] + bsv[jq*4+0];
            v.y = acc[i][jq*4+1] + bsv[jq*4+1];
            v.z = acc[i][jq*4+2] + bsv[jq*4+2];
            v.w = acc[i][jq*4+3] + bsv[jq*4+3];
            if (do_relu) {
                v.x = fmaxf(v.x, 0.f); v.y = fmaxf(v.y, 0.f);
                v.z = fmaxf(v.z, 0.f); v.w = fmaxf(v.w, 0.f);
            }
            *(float4*)(crow + jq*4) = v;
        }
    }
}

// ================= persistent GRU, batch-split pipelined barriers =================
// Half A = batches 0-7, half B = batches 8-15. Separate grid barriers; the wait
// for one half's h-exchange overlaps the other half's compute.
__device__ __forceinline__ void barrier_arrive(unsigned* cnt, unsigned* gen) {
    __threadfence();
    unsigned old = atomicAdd(cnt, 1);
    if (old == GRU_BLOCKS - 1) {
        *cnt = 0;
        __threadfence();
        atomicAdd(gen, 1);
    }
}
__device__ __forceinline__ void barrier_spin(unsigned* gen, unsigned target) {
    while (*(volatile unsigned*)gen < target) __nanosleep(32);
    __threadfence();
}

__global__ void __launch_bounds__(256) gru_persistent_kernel(
    const float* __restrict__ W_hh,
    const float* __restrict__ b_hh)
{
    extern __shared__ float smf[];
    float* W_s  = smf;                 // 24*1024
    float* hA_s = smf + 24*1024;       // 8*1024   batches 0-7
    float* hB_s = hA_s + 8*1024;       // 8*1024   batches 8-15

    const int tid  = threadIdx.x;
    const int w    = tid >> 5;
    const int lane = tid & 31;
    const int blk  = blockIdx.x;
    const int j    = blk * 8 + w;

    for (int idx = tid; idx < 24 * 256; idx += 256) {
        const int r = idx >> 8;
        const int q = idx & 255;
        const int g = r >> 3, wr = r & 7;
        *(float4*)&W_s[r*1024 + q*4] =
            *(const float4*)&W_hh[((size_t)(g*Hh + blk*8 + wr))*Hh + q*4];
    }
    for (int i = tid; i < 16*1024/4; i += 256)
        ((float4*)hA_s)[i] = make_float4(0.f,0.f,0.f,0.f);
    __syncthreads();

    const float* wr_s = W_s + (0*8 + w) * 1024;
    const float* wz_s = W_s + (1*8 + w) * 1024;
    const float* wn_s = W_s + (2*8 + w) * 1024;
    const float bhr = b_hh[j], bhz = b_hh[j + Hh], bhn = b_hh[j + 2*Hh];

    unsigned tgtA = 0, tgtB = 0;

    for (int t = 0; t < Tt; t++) {
#pragma unroll
        for (int half = 0; half < 2; half++) {
            const float* h_half = half ? hB_s : hA_s;
            const int bbase = half * 8;

            // ---- restage this half's h_{t-1} (written by all blocks) ----
            if (half == 0) {
                if (t > 0) {
                    if (tid == 0) barrier_spin(&g_genA, tgtA);
                    __syncthreads();
                    for (int i = tid*4; i < 8*1024; i += 1024) {
                        const int b = i >> 10, k = i & 1023;
                        *(float4*)&hA_s[i] =
                            __ldcg((const float4*)&g_hs[((size_t)(b*Tt + t - 1))*Hh + k]);
                    }
                    __syncthreads();
                }
            } else {
                if (t > 0) {
                    if (tid == 0) barrier_spin(&g_genB, tgtB);
                    __syncthreads();
                    for (int i = tid*4; i < 8*1024; i += 1024) {
                        const int b = i >> 10, k = i & 1023;
                        *(float4*)&hB_s[i] =
                            __ldcg((const float4*)&g_hs[((size_t)((8 + b)*Tt + t - 1))*Hh + k]);
                    }
                    __syncthreads();
                }
            }

            // ---- gi prefetch ----
            float ir = 0.f, iz = 0.f, inn = 0.f;
            if (lane < 8) {
                const float* gi = g_gi + ((size_t)((bbase + lane)*Tt + t)) * G3;
                ir  = __ldcg(gi + j);
                iz  = __ldcg(gi + j + Hh);
                inn = __ldcg(gi + j + 2*Hh);
            }

            // ---- gh = W_hh @ h for 8 batches ----
            unsigned long long ar2[8], az2[8], an2[8];
#pragma unroll
            for (int b = 0; b < 8; b++) { ar2[b] = 0ull; az2[b] = 0ull; an2[b] = 0ull; }

#pragma unroll 4
            for (int i = 0; i < 16; i++) {
                const int k2 = i*64 + lane*2;
                const unsigned long long vr = *(const unsigned long long*)&wr_s[k2];
                const unsigned long long vz = *(const unsigned long long*)&wz_s[k2];
                const unsigned long long vn = *(const unsigned long long*)&wn_s[k2];
#pragma unroll
                for (int b = 0; b < 8; b++) {
                    const unsigned long long hv = *(const unsigned long long*)&h_half[b*1024 + k2];
                    fma2(ar2[b], vr, hv);
                    fma2(az2[b], vz, hv);
                    fma2(an2[b], vn, hv);
                }
            }

            float ar[8], az[8], an[8];
#pragma unroll
            for (int b = 0; b < 8; b++) {
                ar[b] = sum2(ar2[b]);
                az[b] = sum2(az2[b]);
                an[b] = sum2(an2[b]);
            }
#pragma unroll
            for (int b = 0; b < 8; b++) {
#pragma unroll
                for (int o = 16; o > 0; o >>= 1) {
                    ar[b] += __shfl_xor_sync(0xffffffffu, ar[b], o);
                    az[b] += __shfl_xor_sync(0xffffffffu, az[b], o);
                    an[b] += __shfl_xor_sync(0xffffffffu, an[b], o);
                }
            }

            if (lane < 8) {
                const int b = bbase + lane;
                const float r = 1.f / (1.f + expf(-(ir + ar[lane] + bhr)));
                const float z = 1.f / (1.f + expf(-(iz + az[lane] + bhz)));
                const float n = tanhf(inn + r * (an[lane] + bhn));
                const float hp = h_half[lane*1024 + j];
                const float h_new = (1.f - z)*n + z*hp;
                g_hs[((size_t)(b*Tt + t))*Hh + j] = h_new;
                g_hsb[((size_t)(b*Tt + t))*Hh + j] = __float2bfloat16(h_new);
            }
            __syncthreads();
            if (tid == 0) {
                if (half == 0) barrier_arrive(&g_cntA, &g_genA);
                else           barrier_arrive(&g_cntB, &g_genB);
            }
            if (half == 0) tgtA++; else tgtB++;
        }
    }
}

// ================= fused log-softmax (in place) =================
__global__ void __launch_bounds__(256) logsoftmax_kernel(float* __restrict__ out)
{
    extern __shared__ float row_s[];
    const int row = blockIdx.x;
    const int tid = threadIdx.x;
    float* x = out + (size_t)row * Vv;

    float m = -INFINITY, s = 0.f;
    for (int v4 = tid; v4 < Vv/4; v4 += 256) {
        const float4 val = __ldcg((const float4*)x + v4);
        *((float4*)row_s + v4) = val;
        const float vm = fmaxf(fmaxf(val.x, val.y), fmaxf(val.z, val.w));
        if (vm > m) { s *= expf(m - vm); m = vm; }
        s += expf(val.x - m) + expf(val.y - m) + expf(val.z - m) + expf(val.w - m);
    }

    __shared__ float sm[256], ss[256];
    sm[tid] = m; ss[tid] = s;
    __syncthreads();
    for (int o = 128; o > 0; o >>= 1) {
        if (tid < o) {
            const float m2 = sm[tid + o], s2 = ss[tid + o];
            const float M_ = fmaxf(sm[tid], m2);
            ss[tid] = ss[tid]*expf(sm[tid]-M_) + s2*expf(m2-M_);
            sm[tid] = M_;
        }
        __syncthreads();
    }
    const float lse = sm[0] + logf(ss[0]);

    for (int v4 = tid; v4 < Vv/4; v4 += 256) {
        float4 val = *((float4*)row_s + v4);
        val.x -= lse; val.y -= lse; val.z -= lse; val.w -= lse;
        ((float4*)x)[v4] = val;
    }
}

__global__ void hidden_copy_kernel(float* __restrict__ out)
{
    const int i = blockIdx.x * blockDim.x + threadIdx.x;
    const int b = i >> 10;
    const int j = i & (Hh - 1);
    out[(size_t)Mm*Vv + i] = g_hs[((size_t)(b*Tt + Tt - 1))*Hh + j];
}

// ============================================================
extern "C" void kernel_launch(void* const* d_in, const int* in_sizes, int n_in,
                              void* d_out, int out_size)
{
    const int*   inputs = (const int*)  d_in[0];
    const float* emb    = (const float*)d_in[1];
    const float* W_ih   = (const float*)d_in[2];
    const float* W_hh   = (const float*)d_in[3];
    const float* b_ih   = (const float*)d_in[4];
    const float* b_hh   = (const float*)d_in[5];
    const float* W1     = (const float*)d_in[6];
    const float* b1     = (const float*)d_in[7];
    const float* W2     = (const float*)d_in[8];
    const float* b2     = (const float*)d_in[9];
    float* out = (float*)d_out;

    float *p_gi;
    __nv_bfloat16 *p_W1b, *p_W2b, *p_hsb, *p_yb;
    cudaGetSymbolAddress((void**)&p_gi,  g_gi);
    cudaGetSymbolAddress((void**)&p_W1b, g_W1b);
    cudaGetSymbolAddress((void**)&p_W2b, g_W2b);
    cudaGetSymbolAddress((void**)&p_hsb, g_hsb);
    cudaGetSymbolAddress((void**)&p_yb,  g_yb);

    const int gru_smem = (24*1024 + 16*1024) * 4;   // 163840 B
    const int ls_smem  = Vv * 4;                    // 128000 B
    cudaFuncSetAttribute(gru_persistent_kernel,
                         cudaFuncAttributeMaxDynamicSharedMemorySize, gru_smem);
    cudaFuncSetAttribute(hmma_gemm_kernel,
                         cudaFuncAttributeMaxDynamicSharedMemorySize, HG_SMEM);
    cudaFuncSetAttribute(logsoftmax_kernel,
                         cudaFuncAttributeMaxDynamicSharedMemorySize, ls_smem);

    // 0) weight -> bf16
    f2bf_kernel<<<(Hh*Hh)/1024, 256>>>(W1, p_W1b, (Hh*Hh)/4);
    f2bf_kernel<<<((size_t)Vv*Hh)/1024, 256>>>(W2, p_W2b, (Vv*Hh)/4);

    // 1) gi = gather(emb) @ W_ih^T + b_ih  (fp32)
    {
        dim3 grid(G3/128, Mm/128);
        sgemm_kernel<<<grid, 256>>>(emb, W_ih, b_ih, p_gi, Mm, G3, Ee, inputs, 0);
    }

    // 2) GRU scan — persistent, batch-split pipelined barriers
    gru_persistent_kernel<<<GRU_BLOCKS, 256, gru_smem>>>(W_hh, b_hh);

    // 3) y = relu(hs @ W1^T + b1) -> bf16 directly
    {
        dim3 grid(Hh/128, Mm/128);
        hmma_gemm_kernel<<<grid, 256, HG_SMEM>>>(p_hsb, p_W1b, b1, p_yb, Mm, Hh, Hh, 1, 1);
    }

    // 4) logits = y @ W2^T + b2 -> fp32 d_out
    {
        dim3 grid(Vv/128, Mm/128);
        hmma_gemm_kernel<<<grid, 256, HG_SMEM>>>(p_yb, p_W2b, b2, out, Mm, Vv, Hh, 0, 0);
    }

    // 5) fused log_softmax in place
    logsoftmax_kernel<<<Mm, 256, ls_smem>>>(out);

    // 6) hidden
    hidden_copy_kernel<<<(Bb*Hh)/256, 256>>>(out);
}

// round 7
// speedup vs baseline: 1.0044x; 1.0044x over previous
#include <cuda_runtime.h>
#include <cuda_bf16.h>
#include <math.h>
#include <cstdint>

#define Bb 16
#define Tt 256
#define Ee 512
#define Hh 1024
#define Vv 32000
#define G3 3072
#define Mm (Bb*Tt)   // 4096

#define GRU_BLOCKS 128

// ---- scratch ----
__device__ float g_gi[(size_t)Mm*G3];
__device__ float g_hs[(size_t)Mm*Hh];
__device__ __nv_bfloat16 g_W1b[(size_t)Hh*Hh];
__device__ __nv_bfloat16 g_W2b[(size_t)Vv*Hh];
__device__ __nv_bfloat16 g_hsb[(size_t)Mm*Hh];
__device__ __nv_bfloat16 g_yb [(size_t)Mm*Hh];
__device__ int g_flags[GRU_BLOCKS * 8];   // 32B-padded per-block arrival flags
__device__ int g_gen;                     // release generation

__device__ __forceinline__ uint32_t smem_u32(const void* p) {
    uint32_t a;
    asm("{ .reg .u64 t; cvta.to.shared.u64 t, %1; cvt.u32.u64 %0, t; }" : "=r"(a) : "l"(p));
    return a;
}
__device__ __forceinline__ void fma2(unsigned long long& d, unsigned long long a, unsigned long long b) {
    asm("fma.rn.f32x2 %0, %1, %2, %0;" : "+l"(d) : "l"(a), "l"(b));
}
__device__ __forceinline__ float sum2(unsigned long long v) {
    float lo, hi;
    asm("mov.b64 {%0, %1}, %2;" : "=f"(lo), "=f"(hi) : "l"(v));
    return lo + hi;
}

// ================= fp32 -> bf16 (weights only) =================
__global__ void f2bf_kernel(const float* __restrict__ x, __nv_bfloat16* __restrict__ o, int n4)
{
    int i = blockIdx.x * blockDim.x + threadIdx.x;
    if (i >= n4) return;
    float4 v = ((const float4*)x)[i];
    __nv_bfloat162* p = (__nv_bfloat162*)o + i * 2;
    p[0] = __floats2bfloat162_rn(v.x, v.y);
    p[1] = __floats2bfloat162_rn(v.z, v.w);
}

// ================= HMMA bf16 GEMM, 3-stage cp.async pipeline =================
#define HG_STRIDE  40
#define HG_ATILE   (128 * HG_STRIDE * 2)    // 10240 B
#define HG_STAGE   (2 * HG_ATILE)           // 20480 B
#define HG_NSTG    3
#define HG_SMEM    (HG_NSTG * HG_STAGE)     // 61440 B

__device__ __forceinline__ void ldsm_x4(uint32_t* r, uint32_t addr) {
    asm volatile("ldmatrix.sync.aligned.m8n8.x4.shared.b16 {%0,%1,%2,%3}, [%4];"
                 : "=r"(r[0]), "=r"(r[1]), "=r"(r[2]), "=r"(r[3]) : "r"(addr));
}
__device__ __forceinline__ void mma16816(float* d, const uint32_t* a, uint32_t b0, uint32_t b1) {
    asm volatile("mma.sync.aligned.m16n8k16.row.col.f32.bf16.bf16.f32 "
                 "{%0,%1,%2,%3}, {%4,%5,%6,%7}, {%8,%9}, {%0,%1,%2,%3};"
                 : "+f"(d[0]), "+f"(d[1]), "+f"(d[2]), "+f"(d[3])
                 : "r"(a[0]), "r"(a[1]), "r"(a[2]), "r"(a[3]), "r"(b0), "r"(b1));
}
__device__ __forceinline__ void cp_async16(uint32_t saddr, const void* gaddr) {
    asm volatile("cp.async.cg.shared.global [%0], [%1], 16;" :: "r"(saddr), "l"(gaddr));
}

__global__ void __launch_bounds__(256) hmma_gemm_kernel(
    const __nv_bfloat16* __restrict__ A,
    const __nv_bfloat16* __restrict__ Bm,
    const float* __restrict__ bias,
    void* __restrict__ Cv,
    int M, int N, int K, int do_relu, int out_bf16)
{
    extern __shared__ char smem[];
    const uint32_t sb = smem_u32(smem);
    const int tid  = threadIdx.x;
    const int wid  = tid >> 5;
    const int lane = tid & 31;
    const int bn = blockIdx.x, bm = blockIdx.y;

    const int warp_m = wid & 3;
    const int warp_n = wid >> 2;

    float d[2][8][4];
#pragma unroll
    for (int i = 0; i < 2; i++)
#pragma unroll
        for (int j = 0; j < 8; j++)
#pragma unroll
            for (int q = 0; q < 4; q++) d[i][j][q] = 0.f;

    const int NK = K >> 5;
    const int lmat = lane >> 3;
    const int lrow = lane & 7;

    auto load_stage = [&](int it, int buf) {
        const int kt = it << 5;
        const uint32_t sa = sb + buf * HG_STAGE;
        const uint32_t sbB = sa + HG_ATILE;
#pragma unroll
        for (int s = 0; s < 2; s++) {
            const int idx = tid + s * 256;
            const int row = idx >> 2, c = idx & 3;
            cp_async16(sa + row * (HG_STRIDE*2) + c * 16,
                       A + (size_t)(bm * 128 + row) * K + kt + c * 8);
            cp_async16(sbB + row * (HG_STRIDE*2) + c * 16,
                       Bm + (size_t)(bn * 128 + row) * K + kt + c * 8);
        }
        asm volatile("cp.async.commit_group;");
    };

    load_stage(0, 0);
    load_stage(1, 1);

    for (int it = 0; it < NK; it++) {
        asm volatile("cp.async.wait_group 1;");   // stage it complete
        __syncthreads();                           // all warps past compute(it-1)
        if (it + 2 < NK) load_stage(it + 2, (it + 2) % HG_NSTG);

        const uint32_t sa  = sb + (it % HG_NSTG) * HG_STAGE;
        const uint32_t sbB = sa + HG_ATILE;

#pragma unroll
        for (int ks = 0; ks < 2; ks++) {
            uint32_t a[2][4];
#pragma unroll
            for (int mt = 0; mt < 2; mt++) {
                const int row = warp_m * 32 + mt * 16 + (lmat & 1) * 8 + lrow;
                const int c   = ks * 2 + (lmat >> 1);
                ldsm_x4(a[mt], sa + row * (HG_STRIDE*2) + c * 16);
            }
            uint32_t b[4][4];
#pragma unroll
            for (int nt = 0; nt < 4; nt++) {
                const int n = warp_n * 64 + nt * 16 + (lmat >> 1) * 8 + lrow;
                const int c = ks * 2 + (lmat & 1);
                ldsm_x4(b[nt], sbB + n * (HG_STRIDE*2) + c * 16);
            }
#pragma unroll
            for (int mt = 0; mt < 2; mt++)
#pragma unroll
                for (int nt = 0; nt < 4; nt++) {
                    mma16816(d[mt][nt*2+0], a[mt], b[nt][0], b[nt][1]);
                    mma16816(d[mt][nt*2+1], a[mt], b[nt][2], b[nt][3]);
                }
        }
    }

#pragma unroll
    for (int mt = 0; mt < 2; mt++) {
        const int row0 = bm * 128 + warp_m * 32 + mt * 16 + (lane >> 2);
#pragma unroll
        for (int nt8 = 0; nt8 < 8; nt8++) {
            const int col = bn * 128 + warp_n * 64 + nt8 * 8 + (lane & 3) * 2;
            const float b0 = bias[col], b1 = bias[col + 1];
            float2 v0, v1;
            v0.x = d[mt][nt8][0] + b0; v0.y = d[mt][nt8][1] + b1;
            v1.x = d[mt][nt8][2] + b0; v1.y = d[mt][nt8][3] + b1;
            if (do_relu) {
                v0.x = fmaxf(v0.x, 0.f); v0.y = fmaxf(v0.y, 0.f);
                v1.x = fmaxf(v1.x, 0.f); v1.y = fmaxf(v1.y, 0.f);
            }
            if (out_bf16) {
                __nv_bfloat162* C = (__nv_bfloat162*)Cv;
                C[((size_t)row0 * N + col) >> 1]       = __floats2bfloat162_rn(v0.x, v0.y);
                C[((size_t)(row0 + 8) * N + col) >> 1] = __floats2bfloat162_rn(v1.x, v1.y);
            } else {
                float* C = (float*)Cv;
                *(float2*)(C + (size_t)row0 * N + col)       = v0;
                *(float2*)(C + (size_t)(row0 + 8) * N + col) = v1;
            }
        }
    }
}

// ================= fp32 SIMT SGEMM (gi, gathered A) =================
__global__ void sgemm_kernel(const float* __restrict__ A,
                             const float* __restrict__ Bm,
                             const float* __restrict__ bias,
                             float* __restrict__ C,
                             int M, int N, int K,
                             const int* __restrict__ gidx,
                             int do_relu)
{
    __shared__ float As[8][128];
    __shared__ float Bs[8][128];

    const int tid = threadIdx.x;
    const int bn  = blockIdx.x;
    const int bm  = blockIdx.y;

    const int lrow = tid >> 1;
    const int kq   = (tid & 1) * 4;

    const int arow_g = bm * 128 + lrow;
    const float* Ap = gidx ? (A + (size_t)gidx[arow_g] * K)
                           : (A + (size_t)arow_g * K);
    const float* Bp = Bm + (size_t)(bn * 128 + lrow) * K;

    const int tx = tid & 15;
    const int ty = tid >> 4;
    const int m0 = ty * 8;
    const int n0 = tx * 8;

    float acc[8][8];
#pragma unroll
    for (int i = 0; i < 8; i++)
#pragma unroll
        for (int j = 0; j < 8; j++) acc[i][j] = 0.f;

    for (int kt = 0; kt < K; kt += 8) {
        float4 av = *(const float4*)(Ap + kt + kq);
        float4 bv = *(const float4*)(Bp + kt + kq);
        As[kq+0][lrow] = av.x; As[kq+1][lrow] = av.y;
        As[kq+2][lrow] = av.z; As[kq+3][lrow] = av.w;
        Bs[kq+0][lrow] = bv.x; Bs[kq+1][lrow] = bv.y;
        Bs[kq+2][lrow] = bv.z; Bs[kq+3][lrow] = bv.w;
        __syncthreads();

#pragma unroll
        for (int kk = 0; kk < 8; kk++) {
            float4 a0 = *(const float4*)&As[kk][m0];
            float4 a1 = *(const float4*)&As[kk][m0 + 4];
            float4 b0 = *(const float4*)&Bs[kk][n0];
            float4 b1 = *(const float4*)&Bs[kk][n0 + 4];
            float am[8] = {a0.x,a0.y,a0.z,a0.w,a1.x,a1.y,a1.z,a1.w};
            float bb[8] = {b0.x,b0.y,b0.z,b0.w,b1.x,b1.y,b1.z,b1.w};
#pragma unroll
            for (int i = 0; i < 8; i++)
#pragma unroll
                for (int j = 0; j < 8; j++)
                    acc[i][j] = fmaf(am[i], bb[j], acc[i][j]);
        }
        __syncthreads();
    }

    const int ncol0 = bn * 128 + n0;
    float bsv[8];
#pragma unroll
    for (int j = 0; j < 8; j++) bsv[j] = bias[ncol0 + j];

#pragma unroll
    for (int i = 0; i < 8; i++) {
        const int m = bm * 128 + m0 + i;
        float* crow = C + (size_t)m * N + ncol0;
#pragma unroll
        for (int jq = 0; jq < 2; jq++) {
            float4 v;
            v.x = acc[i][jq*4+0] + bsv[jq*4+0];
            v.y = acc[i][jq*4+1] + bsv[jq*4+1];
            v.z = acc[i][jq*4+2] + bsv[jq*4+2];
            v.w = acc[i][jq*4+3] + bsv[jq*4+3];
            if (do_relu) {
                v.x = fmaxf(v.x, 0.f); v.y = fmaxf(v.y, 0.f);
                v.z = fmaxf(v.z, 0.f); v.w = fmaxf(v.w, 0.f);
            }
            *(float4*)(crow + jq*4) = v;
        }
    }
}

// ================= persistent GRU, flag-based grid barrier =================
__global__ void __launch_bounds__(256) gru_persistent_kernel(
    const float* __restrict__ W_hh,
    const float* __restrict__ b_hh)
{
    extern __shared__ float smf[];
    float* W_s = smf;                 // 24*1024 floats
    float* h_s = smf + 24*1024;       // 16*1024 floats

    const int tid  = threadIdx.x;
    const int w    = tid >> 5;
    const int lane = tid & 31;
    const int blk  = blockIdx.x;
    const int j    = blk * 8 + w;

    for (int idx = tid; idx < 24 * 256; idx += 256) {
        const int r = idx >> 8;
        const int q = idx & 255;
        const int g = r >> 3, wr = r & 7;
        *(float4*)&W_s[r*1024 + q*4] =
            *(const float4*)&W_hh[((size_t)(g*Hh + blk*8 + wr))*Hh + q*4];
    }
    for (int i = tid; i < Bb*Hh/4; i += 256)
        ((float4*)h_s)[i] = make_float4(0.f,0.f,0.f,0.f);
    __syncthreads();

    const float* wr_s = W_s + (0*8 + w) * 1024;
    const float* wz_s = W_s + (1*8 + w) * 1024;
    const float* wn_s = W_s + (2*8 + w) * 1024;
    const float bhr = b_hh[j], bhz = b_hh[j + Hh], bhn = b_hh[j + 2*Hh];

    for (int t = 0; t < Tt; t++) {
        float ir = 0.f, iz = 0.f, inn = 0.f;
        if (lane < 16) {
            const float* gi = g_gi + ((size_t)(lane*Tt + t)) * G3;
            ir  = __ldcg(gi + j);
            iz  = __ldcg(gi + j + Hh);
            inn = __ldcg(gi + j + 2*Hh);
        }

        unsigned long long ar2[16], az2[16], an2[16];
#pragma unroll
        for (int b = 0; b < 16; b++) { ar2[b] = 0ull; az2[b] = 0ull; an2[b] = 0ull; }

#pragma unroll 2
        for (int i = 0; i < 16; i++) {
            const int k2 = i*64 + lane*2;
            const unsigned long long vr = *(const unsigned long long*)&wr_s[k2];
            const unsigned long long vz = *(const unsigned long long*)&wz_s[k2];
            const unsigned long long vn = *(const unsigned long long*)&wn_s[k2];
#pragma unroll
            for (int b = 0; b < 16; b++) {
                const unsigned long long hv = *(const unsigned long long*)&h_s[b*Hh + k2];
                fma2(ar2[b], vr, hv);
                fma2(az2[b], vz, hv);
                fma2(an2[b], vn, hv);
            }
        }

        float ar[16], az[16], an[16];
#pragma unroll
        for (int b = 0; b < 16; b++) {
            ar[b] = sum2(ar2[b]);
            az[b] = sum2(az2[b]);
            an[b] = sum2(an2[b]);
        }

#pragma unroll
        for (int b = 0; b < 16; b++) {
#pragma unroll
            for (int o = 16; o > 0; o >>= 1) {
                ar[b] += __shfl_xor_sync(0xffffffffu, ar[b], o);
                az[b] += __shfl_xor_sync(0xffffffffu, az[b], o);
                an[b] += __shfl_xor_sync(0xffffffffu, an[b], o);
            }
        }

        if (lane < 16) {
            const int b = lane;
            const float r = 1.f / (1.f + expf(-(ir + ar[b] + bhr)));
            const float z = 1.f / (1.f + expf(-(iz + az[b] + bhz)));
            const float n = tanhf(inn + r * (an[b] + bhn));
            const float hp = h_s[b*Hh + j];
            const float h_new = (1.f - z)*n + z*hp;
            g_hs[((size_t)(b*Tt + t))*Hh + j] = h_new;
            g_hsb[((size_t)(b*Tt + t))*Hh + j] = __float2bfloat16(h_new);
        }

        if (t + 1 < Tt) {
            // ---- arrive: parallel per-block flags ----
            __syncthreads();
            if (tid == 0) {
                __threadfence();
                *(volatile int*)&g_flags[blk * 8] = t + 1;
            }
            // ---- release / wait ----
            if (blk == 0) {
                if (tid < GRU_BLOCKS) {
                    while (*(volatile int*)&g_flags[tid * 8] < t + 1) __nanosleep(32);
                }
                __syncthreads();
                if (tid == 0) { __threadfence(); *(volatile int*)&g_gen = t + 1; }
            } else {
                if (tid == 0) {
                    while (*(volatile int*)&g_gen < t + 1) __nanosleep(32);
                    __threadfence();
                }
                __syncthreads();
            }
            // ---- restage h_t ----
            for (int i = tid*4; i < Bb*Hh; i += 256*4) {
                const int b = i >> 10;
                const int k = i & (Hh-1);
                *(float4*)&h_s[i] =
                    __ldcg((const float4*)&g_hs[((size_t)(b*Tt + t))*Hh + k]);
            }
            __syncthreads();
        }
    }

    // ---- ack + reset so graph replays start from a clean state ----
    __syncthreads();
    if (tid == 0) { __threadfence(); *(volatile int*)&g_flags[blk * 8] = 0; }
    if (blk == 0) {
        if (tid < GRU_BLOCKS) {
            while (*(volatile int*)&g_flags[tid * 8] != 0) __nanosleep(32);
        }
        __syncthreads();
        if (tid == 0) *(volatile int*)&g_gen = 0;
    }
}

// ================= fused log-softmax (in place) =================
__global__ void __launch_bounds__(256) logsoftmax_kernel(float* __restrict__ out)
{
    extern __shared__ float row_s[];
    const int row = blockIdx.x;
    const int tid = threadIdx.x;
    float* x = out + (size_t)row * Vv;

    float m = -INFINITY, s = 0.f;
    for (int v4 = tid; v4 < Vv/4; v4 += 256) {
        const float4 val = __ldcg((const float4*)x + v4);
        *((float4*)row_s + v4) = val;
        const float vm = fmaxf(fmaxf(val.x, val.y), fmaxf(val.z, val.w));
        if (vm > m) { s *= expf(m - vm); m = vm; }
        s += expf(val.x - m) + expf(val.y - m) + expf(val.z - m) + expf(val.w - m);
    }

    __shared__ float sm[256], ss[256];
    sm[tid] = m; ss[tid] = s;
    __syncthreads();
    for (int o = 128; o > 0; o >>= 1) {
        if (tid < o) {
            const float m2 = sm[tid + o], s2 = ss[tid + o];
            const float M_ = fmaxf(sm[tid], m2);
            ss[tid] = ss[tid]*expf(sm[tid]-M_) + s2*expf(m2-M_);
            sm[tid] = M_;
        }
        __syncthreads();
    }
    const float lse = sm[0] + logf(ss[0]);

    for (int v4 = tid; v4 < Vv/4; v4 += 256) {
        float4 val = *((float4*)row_s + v4);
        val.x -= lse; val.y -= lse; val.z -= lse; val.w -= lse;
        ((float4*)x)[v4] = val;
    }
}

__global__ void hidden_copy_kernel(float* __restrict__ out)
{
    const int i = blockIdx.x * blockDim.x + threadIdx.x;
    const int b = i >> 10;
    const int j = i & (Hh - 1);
    out[(size_t)Mm*Vv + i] = g_hs[((size_t)(b*Tt + Tt - 1))*Hh + j];
}

// ============================================================
extern "C" void kernel_launch(void* const* d_in, const int* in_sizes, int n_in,
                              void* d_out, int out_size)
{
    const int*   inputs = (const int*)  d_in[0];
    const float* emb    = (const float*)d_in[1];
    const float* W_ih   = (const float*)d_in[2];
    const float* W_hh   = (const float*)d_in[3];
    const float* b_ih   = (const float*)d_in[4];
    const float* b_hh   = (const float*)d_in[5];
    const float* W1     = (const float*)d_in[6];
    const float* b1     = (const float*)d_in[7];
    const float* W2     = (const float*)d_in[8];
    const float* b2     = (const float*)d_in[9];
    float* out = (float*)d_out;

    float *p_gi;
    __nv_bfloat16 *p_W1b, *p_W2b, *p_hsb, *p_yb;
    cudaGetSymbolAddress((void**)&p_gi,  g_gi);
    cudaGetSymbolAddress((void**)&p_W1b, g_W1b);
    cudaGetSymbolAddress((void**)&p_W2b, g_W2b);
    cudaGetSymbolAddress((void**)&p_hsb, g_hsb);
    cudaGetSymbolAddress((void**)&p_yb,  g_yb);

    const int gru_smem = (24*1024 + 16*1024) * 4;   // 163840 B
    const int ls_smem  = Vv * 4;                    // 128000 B
    cudaFuncSetAttribute(gru_persistent_kernel,
                         cudaFuncAttributeMaxDynamicSharedMemorySize, gru_smem);
    cudaFuncSetAttribute(hmma_gemm_kernel,
                         cudaFuncAttributeMaxDynamicSharedMemorySize, HG_SMEM);
    cudaFuncSetAttribute(logsoftmax_kernel,
                         cudaFuncAttributeMaxDynamicSharedMemorySize, ls_smem);

    // 0) weight -> bf16
    f2bf_kernel<<<(Hh*Hh)/1024, 256>>>(W1, p_W1b, (Hh*Hh)/4);
    f2bf_kernel<<<((size_t)Vv*Hh)/1024, 256>>>(W2, p_W2b, (Vv*Hh)/4);

    // 1) gi = gather(emb) @ W_ih^T + b_ih  (fp32)
    {
        dim3 grid(G3/128, Mm/128);
        sgemm_kernel<<<grid, 256>>>(emb, W_ih, b_ih, p_gi, Mm, G3, Ee, inputs, 0);
    }

    // 2) GRU scan — persistent, flag-based barrier
    gru_persistent_kernel<<<GRU_BLOCKS, 256, gru_smem>>>(W_hh, b_hh);

    // 3) y = relu(hs @ W1^T + b1) -> bf16 directly
    {
        dim3 grid(Hh/128, Mm/128);
        hmma_gemm_kernel<<<grid, 256, HG_SMEM>>>(p_hsb, p_W1b, b1, p_yb, Mm, Hh, Hh, 1, 1);
    }

    // 4) logits = y @ W2^T + b2 -> fp32 d_out
    {
        dim3 grid(Vv/128, Mm/128);
        hmma_gemm_kernel<<<grid, 256, HG_SMEM>>>(p_yb, p_W2b, b2, out, Mm, Vv, Hh, 0, 0);
    }

    // 5) fused log_softmax in place
    logsoftmax_kernel<<<Mm, 256, ls_smem>>>(out);

    // 6) hidden
    hidden_copy_kernel<<<(Bb*Hh)/256, 256>>>(out);
}